// round 6
// baseline (speedup 1.0000x reference)
#include <cuda_runtime.h>
#include <cuda_fp16.h>
#include <cstdint>

#define NTOK 16384
#define HDIM 1024
#define MDIM 512
#define NEXP 8
#define MAX_TILES 144
#define NC 32                 // K chunks of 32
#define TILE_PB 10240         // one padded tile: 128 rows * 80B
#define ROW_PB 80             // padded row bytes (32 fp16 + 8 pad)
#define MAXFLAG 4096
#define GAP_THRESH 8e-3f

// ---------------- scratch ----------------
__device__ float  g_h[NTOK * MDIM];
__device__ __half g_X1[NTOK * HDIM];
__device__ __half g_W1a[MDIM * HDIM];
__device__ __half g_W2a[NEXP * HDIM * HDIM];
__device__ int g_idx[NTOK];
__device__ int g_counts[NEXP];
__device__ int g_base[NEXP];
__device__ int g_cursor[NEXP];
__device__ int g_perm[NTOK];
__device__ int g_tile_e[MAX_TILES];
__device__ int g_tile_r[MAX_TILES];
__device__ int g_tile_n[MAX_TILES];
__device__ int g_numtiles;
__device__ int g_flag[MAXFLAG];
__device__ int g_nflag;

// ---------------- helpers ----------------
__device__ __forceinline__ uint32_t smem_u32(const void* p) {
    uint32_t a;
    asm("{ .reg .u64 t; cvta.to.shared.u64 t, %1; cvt.u32.u64 %0, t; }" : "=r"(a) : "l"(p));
    return a;
}
__device__ __forceinline__ void cp16(uint32_t s, const void* g) {
    asm volatile("cp.async.cg.shared.global [%0], [%1], 16;" :: "r"(s), "l"(g));
}
#define CP_COMMIT() asm volatile("cp.async.commit_group;" ::: "memory")
#define CP_WAIT1()  asm volatile("cp.async.wait_group 1;" ::: "memory")
__device__ __forceinline__ void ldsm4(uint32_t r[4], uint32_t a) {
    asm volatile("ldmatrix.sync.aligned.m8n8.x4.shared.b16 {%0,%1,%2,%3}, [%4];"
                 : "=r"(r[0]), "=r"(r[1]), "=r"(r[2]), "=r"(r[3]) : "r"(a));
}
__device__ __forceinline__ void mma16816(float c[4], const uint32_t a[4], const uint32_t b[2]) {
    asm volatile(
        "mma.sync.aligned.m16n8k16.row.col.f32.f16.f16.f32 "
        "{%0,%1,%2,%3}, {%4,%5,%6,%7}, {%8,%9}, {%0,%1,%2,%3};"
        : "+f"(c[0]), "+f"(c[1]), "+f"(c[2]), "+f"(c[3])
        : "r"(a[0]), "r"(a[1]), "r"(a[2]), "r"(a[3]), "r"(b[0]), "r"(b[1]));
}

// ---------------- init ----------------
__global__ void k_init() {
    int t = threadIdx.x;
    if (t < NEXP) { g_counts[t] = 0; g_cursor[t] = 0; }
    if (t == 0) g_nflag = 0;
}

// ---------------- X -> fp16 (rounded) ----------------
__global__ __launch_bounds__(256) void k_convA(const float* __restrict__ X) {
    int i = blockIdx.x * 256 + threadIdx.x;  // float4 index
    float4 v = ((const float4*)X)[i];
    __align__(8) __half a1[4];
    a1[0] = __float2half_rn(v.x); a1[1] = __float2half_rn(v.y);
    a1[2] = __float2half_rn(v.z); a1[3] = __float2half_rn(v.w);
    ((uint2*)g_X1)[i] = *(uint2*)a1;
}

// ---------------- w1 [K][N] -> [N][K] fp16 ----------------
__global__ void k_convW1(const float* __restrict__ src) {
    __shared__ float t[32][33];
    int n0 = blockIdx.x * 32, k0 = blockIdx.y * 32;
    int tx = threadIdx.x, ty = threadIdx.y;
#pragma unroll
    for (int j = 0; j < 4; j++)
        t[ty + 8 * j][tx] = src[(size_t)(k0 + ty + 8 * j) * MDIM + n0 + tx];
    __syncthreads();
#pragma unroll
    for (int j = 0; j < 4; j++) {
        int rr = ty + 8 * j;
        g_W1a[(size_t)(n0 + rr) * HDIM + k0 + tx] = __float2half_rn(t[tx][rr]);
    }
}

// ---------------- expert_W [E][K][N] -> [E][N][K] fp16 ----------------
__global__ void k_convW2(const float* __restrict__ src) {
    __shared__ float t[32][33];
    int e = blockIdx.z;
    const float* s = src + ((size_t)e << 20);
    __half* d1 = g_W2a + ((size_t)e << 20);
    int n0 = blockIdx.x * 32, k0 = blockIdx.y * 32;
    int tx = threadIdx.x, ty = threadIdx.y;
#pragma unroll
    for (int j = 0; j < 4; j++)
        t[ty + 8 * j][tx] = s[(size_t)(k0 + ty + 8 * j) * HDIM + n0 + tx];
    __syncthreads();
#pragma unroll
    for (int j = 0; j < 4; j++) {
        int rr = ty + 8 * j;
        d1[(size_t)(n0 + rr) * HDIM + k0 + tx] = __float2half_rn(t[tx][rr]);
    }
}

// ---------------- single-pass fp16 GEMM (mma.sync), 2 tiles/stage ------------
template <bool GATHER>
__global__ __launch_bounds__(256) void k_gemm_mma(const float* __restrict__ biasg,
                                                  float* __restrict__ outg) {
    constexpr int STAGE = 2 * TILE_PB;   // A + B
    __shared__ float sbias[128];
    __shared__ int tks[128];
    extern __shared__ char dsm[];
    const uint32_t sb = smem_u32(dsm);

    const int tid = threadIdx.x;
    const int wid = tid >> 5;
    const int lane = tid & 31;
    const int warp_m = wid >> 2;   // 0..1
    const int warp_n = wid & 3;    // 0..3

    int row0 = 0, nrows = 128, col0 = blockIdx.y * 128;
    const __half *A1, *B1;
    if (GATHER) {
        const int tile = blockIdx.x;
        if (tile >= g_numtiles) return;
        const int e = g_tile_e[tile];
        const int grs = g_tile_r[tile];
        nrows = g_tile_n[tile];
        if (tid < 128) {
            tks[tid] = g_perm[grs + (tid < nrows ? tid : 0)];
            sbias[tid] = biasg[(size_t)e * HDIM + col0 + tid];
        }
        A1 = g_X1;
        B1 = g_W2a + ((size_t)e << 20) + (size_t)col0 * HDIM;
    } else {
        row0 = blockIdx.x * 128;
        if (tid < 128) sbias[tid] = biasg[col0 + tid];
        A1 = g_X1;
        B1 = g_W1a + (size_t)col0 * HDIM;
    }
    __syncthreads();

    // per-thread cp.async mapping: 4 chunks of 16B per stage
    int c_tile[4], c_row[4], c_seg[4];
#pragma unroll
    for (int i = 0; i < 4; i++) {
        int cid = tid + i * 256;
        c_tile[i] = cid >> 9;
        int c2 = cid & 511;
        c_row[i] = c2 >> 2;
        c_seg[i] = c2 & 3;
    }

    auto issue = [&](int buf, int kbase) {
#pragma unroll
        for (int i = 0; i < 4; i++) {
            const int tile = c_tile[i], row = c_row[i], seg = c_seg[i];
            uint32_t sa = sb + buf * STAGE + tile * TILE_PB + row * ROW_PB + seg * 16;
            const __half* src;
            int grow;
            if (tile == 0) { src = A1; grow = GATHER ? tks[row] : row0 + row; }
            else           { src = B1; grow = row; }
            cp16(sa, src + (size_t)grow * HDIM + kbase + seg * 8);
        }
    };

    float acc[4][4][4];
#pragma unroll
    for (int mi = 0; mi < 4; mi++)
#pragma unroll
        for (int ni = 0; ni < 4; ni++)
#pragma unroll
            for (int k = 0; k < 4; k++) acc[mi][ni][k] = 0.0f;

    issue(0, 0);  CP_COMMIT();
    issue(1, 32); CP_COMMIT();

    const int lm = lane & 15, lh = lane >> 4;
    const uint32_t a_off = (uint32_t)((warp_m * 64 + lm) * ROW_PB + lh * 16);
    const uint32_t b_off = (uint32_t)((warp_n * 32 + lm) * ROW_PB + lh * 16);

    for (int c = 0; c < NC; c++) {
        CP_WAIT1();
        __syncthreads();
        const int buf = c & 1;
        const uint32_t sA1 = sb + buf * STAGE;
        const uint32_t sB1 = sA1 + TILE_PB;

#pragma unroll
        for (int kh = 0; kh < 2; kh++) {
            uint32_t a1[4][4], b1f[4][2];
#pragma unroll
            for (int mi = 0; mi < 4; mi++)
                ldsm4(a1[mi], sA1 + a_off + mi * (16 * ROW_PB) + kh * 32);
#pragma unroll
            for (int nt = 0; nt < 2; nt++) {
                uint32_t r[4];
                ldsm4(r, sB1 + b_off + nt * (16 * ROW_PB) + kh * 32);
                b1f[nt * 2][0] = r[0]; b1f[nt * 2][1] = r[2];
                b1f[nt * 2 + 1][0] = r[1]; b1f[nt * 2 + 1][1] = r[3];
            }
#pragma unroll
            for (int mi = 0; mi < 4; mi++)
#pragma unroll
                for (int ni = 0; ni < 4; ni++)
                    mma16816(acc[mi][ni], a1[mi], b1f[ni]);
        }
        __syncthreads();
        if (c + 2 < NC) issue(buf, (c + 2) * 32);
        CP_COMMIT();
    }

    // epilogue
    const int rbase = warp_m * 64 + (lane >> 2);
    const int cbase = warp_n * 32 + (lane & 3) * 2;
#pragma unroll
    for (int mi = 0; mi < 4; mi++) {
#pragma unroll
        for (int ni = 0; ni < 4; ni++) {
            const int r0 = rbase + mi * 16;
            const int cc = cbase + ni * 8;
            float v00 = acc[mi][ni][0] + sbias[cc];
            float v01 = acc[mi][ni][1] + sbias[cc + 1];
            float v10 = acc[mi][ni][2] + sbias[cc];
            float v11 = acc[mi][ni][3] + sbias[cc + 1];
            if (GATHER) {
                if (r0 < nrows) {
                    float* p = outg + (size_t)tks[r0] * HDIM + col0 + cc;
                    *(float2*)p = make_float2(v00, v01);
                }
                if (r0 + 8 < nrows) {
                    float* p = outg + (size_t)tks[r0 + 8] * HDIM + col0 + cc;
                    *(float2*)p = make_float2(v10, v11);
                }
            } else {
                float* p0 = g_h + (size_t)(row0 + r0) * MDIM + col0 + cc;
                float* p1 = g_h + (size_t)(row0 + r0 + 8) * MDIM + col0 + cc;
                *(float2*)p0 = make_float2(fmaxf(v00, 0.f), fmaxf(v01, 0.f));
                *(float2*)p1 = make_float2(fmaxf(v10, 0.f), fmaxf(v11, 0.f));
            }
        }
    }
}

// ---------------- scores + provisional argmax + near-tie flagging ------------
__global__ __launch_bounds__(256) void k_scores(const float* __restrict__ w2,
                                                const float* __restrict__ b2) {
    __shared__ float sw2t[NEXP * MDIM];
    for (int i = threadIdx.x; i < MDIM * NEXP; i += 256) {
        int m = i / NEXP, e = i % NEXP;
        sw2t[e * MDIM + m] = w2[i];
    }
    __syncthreads();
    const int warp = threadIdx.x >> 5, lane = threadIdx.x & 31;
    const int t = blockIdx.x * 8 + warp;
    const float* hrow = g_h + (size_t)t * MDIM;
    float s[NEXP];
#pragma unroll
    for (int e = 0; e < NEXP; e++) s[e] = 0.0f;
    for (int m = lane; m < MDIM; m += 32) {
        float hv = hrow[m];
#pragma unroll
        for (int e = 0; e < NEXP; e++) s[e] = fmaf(hv, sw2t[e * MDIM + m], s[e]);
    }
#pragma unroll
    for (int e = 0; e < NEXP; e++)
#pragma unroll
        for (int off = 16; off; off >>= 1) s[e] += __shfl_xor_sync(0xffffffffu, s[e], off);
    if (lane == 0) {
        int best = 0;
        float bv = s[0] + b2[0], second = -1e30f;
#pragma unroll
        for (int e = 1; e < NEXP; e++) {
            float v = s[e] + b2[e];
            if (v > bv) { second = bv; bv = v; best = e; }
            else if (v > second) second = v;
        }
        g_idx[t] = best;
        if (bv - second < GAP_THRESH) {
            int slot = atomicAdd(&g_nflag, 1);
            if (slot < MAXFLAG) g_flag[slot] = t;
        }
    }
}

// ---------------- exact fp32 rescue for flagged tokens ----------------
__global__ __launch_bounds__(256) void k_rescue(const float* __restrict__ X,
                                                const float* __restrict__ w1,
                                                const float* __restrict__ b1,
                                                const float* __restrict__ w2,
                                                const float* __restrict__ b2) {
    __shared__ float sx[HDIM];
    __shared__ float ssc[NEXP];
    const int tid = threadIdx.x;
    int n = g_nflag;
    if (n > MAXFLAG) n = MAXFLAG;
    for (int i = blockIdx.x; i < n; i += gridDim.x) {
        const int tok = g_flag[i];
        // load X row
        for (int k = tid; k < HDIM; k += 256) sx[k] = X[(size_t)tok * HDIM + k];
        if (tid < NEXP) ssc[tid] = 0.0f;
        __syncthreads();
        float sc[NEXP];
#pragma unroll
        for (int e = 0; e < NEXP; e++) sc[e] = 0.0f;
        // each thread: 2 hidden columns
#pragma unroll
        for (int half = 0; half < 2; half++) {
            const int nc = tid + half * 256;
            float a = 0.0f;
            for (int k = 0; k < HDIM; k++) a = fmaf(sx[k], w1[(size_t)k * MDIM + nc], a);
            a = fmaxf(a + b1[nc], 0.0f);
#pragma unroll
            for (int e = 0; e < NEXP; e++) sc[e] = fmaf(a, w2[nc * NEXP + e], sc[e]);
        }
        // reduce scores across block
#pragma unroll
        for (int e = 0; e < NEXP; e++) {
#pragma unroll
            for (int off = 16; off; off >>= 1) sc[e] += __shfl_xor_sync(0xffffffffu, sc[e], off);
            if ((tid & 31) == 0) atomicAdd(&ssc[e], sc[e]);
        }
        __syncthreads();
        if (tid == 0) {
            int best = 0;
            float bv = ssc[0] + b2[0];
#pragma unroll
            for (int e = 1; e < NEXP; e++) {
                float v = ssc[e] + b2[e];
                if (v > bv) { bv = v; best = e; }
            }
            g_idx[tok] = best;
        }
        __syncthreads();
    }
}

// ---------------- count + scan + fill ----------------
__global__ void k_count() {
    int t = blockIdx.x * 256 + threadIdx.x;
    if (t < NTOK) atomicAdd(&g_counts[g_idx[t]], 1);
}
__global__ void k_scan() {
    int s = 0;
    for (int e = 0; e < NEXP; e++) { g_base[e] = s; s += g_counts[e]; }
    int nt = 0;
    for (int e = 0; e < NEXP; e++) {
        int c = g_counts[e];
        for (int r = 0; r < c; r += 128) {
            g_tile_e[nt] = e;
            g_tile_r[nt] = g_base[e] + r;
            g_tile_n[nt] = (c - r) < 128 ? (c - r) : 128;
            nt++;
        }
    }
    g_numtiles = nt;
}
__global__ void k_fill() {
    int t = blockIdx.x * 256 + threadIdx.x;
    if (t < NTOK) {
        int e = g_idx[t];
        int r = atomicAdd(&g_cursor[e], 1);
        g_perm[g_base[e] + r] = t;
    }
}

// ---------------- launch ----------------
extern "C" void kernel_launch(void* const* d_in, const int* in_sizes, int n_in,
                              void* d_out, int out_size) {
    const float* X  = (const float*)d_in[0];
    const float* w1 = (const float*)d_in[1];
    const float* b1 = (const float*)d_in[2];
    const float* w2 = (const float*)d_in[3];
    const float* b2 = (const float*)d_in[4];
    const float* eW = (const float*)d_in[5];
    const float* eb = (const float*)d_in[6];
    float* out = (float*)d_out;

    const int DSM = 2 * 2 * TILE_PB;  // 40960
    cudaFuncSetAttribute(k_gemm_mma<false>, cudaFuncAttributeMaxDynamicSharedMemorySize, DSM);
    cudaFuncSetAttribute(k_gemm_mma<true>,  cudaFuncAttributeMaxDynamicSharedMemorySize, DSM);

    k_init<<<1, 32>>>();
    k_convA<<<NTOK * HDIM / 1024, 256>>>(X);
    k_convW1<<<dim3(MDIM / 32, HDIM / 32, 1), dim3(32, 8)>>>(w1);
    k_convW2<<<dim3(HDIM / 32, HDIM / 32, NEXP), dim3(32, 8)>>>(eW);
    k_gemm_mma<false><<<dim3(NTOK / 128, MDIM / 128), 256, DSM>>>(b1, nullptr);
    k_scores<<<NTOK / 8, 256>>>(w2, b2);
    k_rescue<<<64, 256>>>(X, w1, b1, w2, b2);
    k_count<<<NTOK / 256, 256>>>();
    k_scan<<<1, 1>>>();
    k_fill<<<NTOK / 256, 256>>>();
    k_gemm_mma<true><<<dim3(MAX_TILES, HDIM / 128), 256, DSM>>>(eb, out);
}

// round 7
// speedup vs baseline: 1.4312x; 1.4312x over previous
#include <cuda_runtime.h>
#include <cuda_fp16.h>
#include <cstdint>

#define NTOK 16384
#define HDIM 1024
#define MDIM 512
#define NEXP 8
#define MAX_TILES 144
#define NC 32                 // K chunks of 32
#define TILE_PB 10240         // one padded tile: 128 rows * 80B
#define ROW_PB 80             // padded row bytes (32 fp16 + 8 pad)
#define MAXFLAG 4096
#define GAP_THRESH 4e-3f

// ---------------- scratch ----------------
__device__ float  g_h[NTOK * MDIM];
__device__ __half g_X1[NTOK * HDIM];
__device__ __half g_W1a[MDIM * HDIM];
__device__ __half g_W2a[NEXP * HDIM * HDIM];
__device__ int g_idx[NTOK];
__device__ int g_counts[NEXP];
__device__ int g_base[NEXP];
__device__ int g_cursor[NEXP];
__device__ int g_perm[NTOK];
__device__ int g_tile_e[MAX_TILES];
__device__ int g_tile_r[MAX_TILES];
__device__ int g_tile_n[MAX_TILES];
__device__ int g_numtiles;
__device__ int g_flag[MAXFLAG];
__device__ int g_nflag;

// ---------------- helpers ----------------
__device__ __forceinline__ uint32_t smem_u32(const void* p) {
    uint32_t a;
    asm("{ .reg .u64 t; cvta.to.shared.u64 t, %1; cvt.u32.u64 %0, t; }" : "=r"(a) : "l"(p));
    return a;
}
__device__ __forceinline__ void cp16(uint32_t s, const void* g) {
    asm volatile("cp.async.cg.shared.global [%0], [%1], 16;" :: "r"(s), "l"(g));
}
#define CP_COMMIT() asm volatile("cp.async.commit_group;" ::: "memory")
#define CP_WAIT1()  asm volatile("cp.async.wait_group 1;" ::: "memory")
__device__ __forceinline__ void ldsm4(uint32_t r[4], uint32_t a) {
    asm volatile("ldmatrix.sync.aligned.m8n8.x4.shared.b16 {%0,%1,%2,%3}, [%4];"
                 : "=r"(r[0]), "=r"(r[1]), "=r"(r[2]), "=r"(r[3]) : "r"(a));
}
__device__ __forceinline__ void mma16816(float c[4], const uint32_t a[4], const uint32_t b[2]) {
    asm volatile(
        "mma.sync.aligned.m16n8k16.row.col.f32.f16.f16.f32 "
        "{%0,%1,%2,%3}, {%4,%5,%6,%7}, {%8,%9}, {%0,%1,%2,%3};"
        : "+f"(c[0]), "+f"(c[1]), "+f"(c[2]), "+f"(c[3])
        : "r"(a[0]), "r"(a[1]), "r"(a[2]), "r"(a[3]), "r"(b[0]), "r"(b[1]));
}

// ---------------- init ----------------
__global__ void k_init() {
    int t = threadIdx.x;
    if (t < NEXP) { g_counts[t] = 0; g_cursor[t] = 0; }
    if (t == 0) g_nflag = 0;
}

// ---------------- X -> fp16 (rounded) ----------------
__global__ __launch_bounds__(256) void k_convA(const float* __restrict__ X) {
    int i = blockIdx.x * 256 + threadIdx.x;  // float4 index
    float4 v = ((const float4*)X)[i];
    __align__(8) __half a1[4];
    a1[0] = __float2half_rn(v.x); a1[1] = __float2half_rn(v.y);
    a1[2] = __float2half_rn(v.z); a1[3] = __float2half_rn(v.w);
    ((uint2*)g_X1)[i] = *(uint2*)a1;
}

// ---------------- w1 [K][N] -> [N][K] fp16 ----------------
__global__ void k_convW1(const float* __restrict__ src) {
    __shared__ float t[32][33];
    int n0 = blockIdx.x * 32, k0 = blockIdx.y * 32;
    int tx = threadIdx.x, ty = threadIdx.y;
#pragma unroll
    for (int j = 0; j < 4; j++)
        t[ty + 8 * j][tx] = src[(size_t)(k0 + ty + 8 * j) * MDIM + n0 + tx];
    __syncthreads();
#pragma unroll
    for (int j = 0; j < 4; j++) {
        int rr = ty + 8 * j;
        g_W1a[(size_t)(n0 + rr) * HDIM + k0 + tx] = __float2half_rn(t[tx][rr]);
    }
}

// ---------------- expert_W [E][K][N] -> [E][N][K] fp16 ----------------
__global__ void k_convW2(const float* __restrict__ src) {
    __shared__ float t[32][33];
    int e = blockIdx.z;
    const float* s = src + ((size_t)e << 20);
    __half* d1 = g_W2a + ((size_t)e << 20);
    int n0 = blockIdx.x * 32, k0 = blockIdx.y * 32;
    int tx = threadIdx.x, ty = threadIdx.y;
#pragma unroll
    for (int j = 0; j < 4; j++)
        t[ty + 8 * j][tx] = s[(size_t)(k0 + ty + 8 * j) * HDIM + n0 + tx];
    __syncthreads();
#pragma unroll
    for (int j = 0; j < 4; j++) {
        int rr = ty + 8 * j;
        d1[(size_t)(n0 + rr) * HDIM + k0 + tx] = __float2half_rn(t[tx][rr]);
    }
}

// ---------------- single-pass fp16 GEMM (mma.sync), 2 tiles/stage ------------
template <bool GATHER>
__global__ __launch_bounds__(256) void k_gemm_mma(const float* __restrict__ biasg,
                                                  float* __restrict__ outg) {
    constexpr int STAGE = 2 * TILE_PB;   // A + B
    __shared__ float sbias[128];
    __shared__ int tks[128];
    extern __shared__ char dsm[];
    const uint32_t sb = smem_u32(dsm);

    const int tid = threadIdx.x;
    const int wid = tid >> 5;
    const int lane = tid & 31;
    const int warp_m = wid >> 2;   // 0..1
    const int warp_n = wid & 3;    // 0..3

    int row0 = 0, nrows = 128, col0 = blockIdx.y * 128;
    const __half *A1, *B1;
    if (GATHER) {
        const int tile = blockIdx.x;
        if (tile >= g_numtiles) return;
        const int e = g_tile_e[tile];
        const int grs = g_tile_r[tile];
        nrows = g_tile_n[tile];
        if (tid < 128) {
            tks[tid] = g_perm[grs + (tid < nrows ? tid : 0)];
            sbias[tid] = biasg[(size_t)e * HDIM + col0 + tid];
        }
        A1 = g_X1;
        B1 = g_W2a + ((size_t)e << 20) + (size_t)col0 * HDIM;
    } else {
        row0 = blockIdx.x * 128;
        if (tid < 128) sbias[tid] = biasg[col0 + tid];
        A1 = g_X1;
        B1 = g_W1a + (size_t)col0 * HDIM;
    }
    __syncthreads();

    // per-thread cp.async mapping: 4 chunks of 16B per stage
    int c_tile[4], c_row[4], c_seg[4];
#pragma unroll
    for (int i = 0; i < 4; i++) {
        int cid = tid + i * 256;
        c_tile[i] = cid >> 9;
        int c2 = cid & 511;
        c_row[i] = c2 >> 2;
        c_seg[i] = c2 & 3;
    }

    auto issue = [&](int buf, int kbase) {
#pragma unroll
        for (int i = 0; i < 4; i++) {
            const int tile = c_tile[i], row = c_row[i], seg = c_seg[i];
            uint32_t sa = sb + buf * STAGE + tile * TILE_PB + row * ROW_PB + seg * 16;
            const __half* src;
            int grow;
            if (tile == 0) { src = A1; grow = GATHER ? tks[row] : row0 + row; }
            else           { src = B1; grow = row; }
            cp16(sa, src + (size_t)grow * HDIM + kbase + seg * 8);
        }
    };

    float acc[4][4][4];
#pragma unroll
    for (int mi = 0; mi < 4; mi++)
#pragma unroll
        for (int ni = 0; ni < 4; ni++)
#pragma unroll
            for (int k = 0; k < 4; k++) acc[mi][ni][k] = 0.0f;

    issue(0, 0);  CP_COMMIT();
    issue(1, 32); CP_COMMIT();

    const int lm = lane & 15, lh = lane >> 4;
    const uint32_t a_off = (uint32_t)((warp_m * 64 + lm) * ROW_PB + lh * 16);
    const uint32_t b_off = (uint32_t)((warp_n * 32 + lm) * ROW_PB + lh * 16);

    for (int c = 0; c < NC; c++) {
        CP_WAIT1();
        __syncthreads();
        const int buf = c & 1;
        const uint32_t sA1 = sb + buf * STAGE;
        const uint32_t sB1 = sA1 + TILE_PB;

#pragma unroll
        for (int kh = 0; kh < 2; kh++) {
            uint32_t a1[4][4], b1f[4][2];
#pragma unroll
            for (int mi = 0; mi < 4; mi++)
                ldsm4(a1[mi], sA1 + a_off + mi * (16 * ROW_PB) + kh * 32);
#pragma unroll
            for (int nt = 0; nt < 2; nt++) {
                uint32_t r[4];
                ldsm4(r, sB1 + b_off + nt * (16 * ROW_PB) + kh * 32);
                b1f[nt * 2][0] = r[0]; b1f[nt * 2][1] = r[2];
                b1f[nt * 2 + 1][0] = r[1]; b1f[nt * 2 + 1][1] = r[3];
            }
#pragma unroll
            for (int mi = 0; mi < 4; mi++)
#pragma unroll
                for (int ni = 0; ni < 4; ni++)
                    mma16816(acc[mi][ni], a1[mi], b1f[ni]);
        }
        __syncthreads();
        if (c + 2 < NC) issue(buf, (c + 2) * 32);
        CP_COMMIT();
    }

    // epilogue
    const int rbase = warp_m * 64 + (lane >> 2);
    const int cbase = warp_n * 32 + (lane & 3) * 2;
#pragma unroll
    for (int mi = 0; mi < 4; mi++) {
#pragma unroll
        for (int ni = 0; ni < 4; ni++) {
            const int r0 = rbase + mi * 16;
            const int cc = cbase + ni * 8;
            float v00 = acc[mi][ni][0] + sbias[cc];
            float v01 = acc[mi][ni][1] + sbias[cc + 1];
            float v10 = acc[mi][ni][2] + sbias[cc];
            float v11 = acc[mi][ni][3] + sbias[cc + 1];
            if (GATHER) {
                if (r0 < nrows) {
                    float* p = outg + (size_t)tks[r0] * HDIM + col0 + cc;
                    *(float2*)p = make_float2(v00, v01);
                }
                if (r0 + 8 < nrows) {
                    float* p = outg + (size_t)tks[r0 + 8] * HDIM + col0 + cc;
                    *(float2*)p = make_float2(v10, v11);
                }
            } else {
                float* p0 = g_h + (size_t)(row0 + r0) * MDIM + col0 + cc;
                float* p1 = g_h + (size_t)(row0 + r0 + 8) * MDIM + col0 + cc;
                *(float2*)p0 = make_float2(fmaxf(v00, 0.f), fmaxf(v01, 0.f));
                *(float2*)p1 = make_float2(fmaxf(v10, 0.f), fmaxf(v11, 0.f));
            }
        }
    }
}

// ---------------- scores + provisional argmax + near-tie flagging ------------
__global__ __launch_bounds__(256) void k_scores(const float* __restrict__ w2,
                                                const float* __restrict__ b2) {
    __shared__ float sw2t[NEXP * MDIM];
    for (int i = threadIdx.x; i < MDIM * NEXP; i += 256) {
        int m = i / NEXP, e = i % NEXP;
        sw2t[e * MDIM + m] = w2[i];
    }
    __syncthreads();
    const int warp = threadIdx.x >> 5, lane = threadIdx.x & 31;
    const int t = blockIdx.x * 8 + warp;
    const float* hrow = g_h + (size_t)t * MDIM;
    float s[NEXP];
#pragma unroll
    for (int e = 0; e < NEXP; e++) s[e] = 0.0f;
    for (int m = lane; m < MDIM; m += 32) {
        float hv = hrow[m];
#pragma unroll
        for (int e = 0; e < NEXP; e++) s[e] = fmaf(hv, sw2t[e * MDIM + m], s[e]);
    }
#pragma unroll
    for (int e = 0; e < NEXP; e++)
#pragma unroll
        for (int off = 16; off; off >>= 1) s[e] += __shfl_xor_sync(0xffffffffu, s[e], off);
    if (lane == 0) {
        int best = 0;
        float bv = s[0] + b2[0], second = -1e30f;
#pragma unroll
        for (int e = 1; e < NEXP; e++) {
            float v = s[e] + b2[e];
            if (v > bv) { second = bv; bv = v; best = e; }
            else if (v > second) second = v;
        }
        g_idx[t] = best;
        if (bv - second < GAP_THRESH) {
            int slot = atomicAdd(&g_nflag, 1);
            if (slot < MAXFLAG) g_flag[slot] = t;
        }
    }
}

// ---------------- exact fp32 rescue (one block per flagged token, ILP4) ------
__global__ __launch_bounds__(256) void k_rescue(const float* __restrict__ X,
                                                const float* __restrict__ w1,
                                                const float* __restrict__ b1,
                                                const float* __restrict__ w2,
                                                const float* __restrict__ b2) {
    __shared__ float sx[HDIM];
    __shared__ float ssc[NEXP];
    const int tid = threadIdx.x;
    int n = g_nflag;
    if (n > MAXFLAG) n = MAXFLAG;
    for (int i = blockIdx.x; i < n; i += gridDim.x) {
        const int tok = g_flag[i];
        for (int k = tid; k < HDIM; k += 256) sx[k] = X[(size_t)tok * HDIM + k];
        if (tid < NEXP) ssc[tid] = 0.0f;
        __syncthreads();
        float sc[NEXP];
#pragma unroll
        for (int e = 0; e < NEXP; e++) sc[e] = 0.0f;
#pragma unroll
        for (int half = 0; half < 2; half++) {
            const int nc = tid + half * 256;
            // 4 independent accumulators + unroll -> 16 loads in flight
            float a0 = 0.f, a1 = 0.f, a2 = 0.f, a3 = 0.f;
#pragma unroll 4
            for (int k = 0; k < HDIM; k += 4) {
                a0 = fmaf(sx[k + 0], __ldg(&w1[(size_t)(k + 0) * MDIM + nc]), a0);
                a1 = fmaf(sx[k + 1], __ldg(&w1[(size_t)(k + 1) * MDIM + nc]), a1);
                a2 = fmaf(sx[k + 2], __ldg(&w1[(size_t)(k + 2) * MDIM + nc]), a2);
                a3 = fmaf(sx[k + 3], __ldg(&w1[(size_t)(k + 3) * MDIM + nc]), a3);
            }
            float a = fmaxf((a0 + a1) + (a2 + a3) + b1[nc], 0.0f);
#pragma unroll
            for (int e = 0; e < NEXP; e++) sc[e] = fmaf(a, w2[nc * NEXP + e], sc[e]);
        }
#pragma unroll
        for (int e = 0; e < NEXP; e++) {
#pragma unroll
            for (int off = 16; off; off >>= 1) sc[e] += __shfl_xor_sync(0xffffffffu, sc[e], off);
            if ((tid & 31) == 0) atomicAdd(&ssc[e], sc[e]);
        }
        __syncthreads();
        if (tid == 0) {
            int best = 0;
            float bv = ssc[0] + b2[0];
#pragma unroll
            for (int e = 1; e < NEXP; e++) {
                float v = ssc[e] + b2[e];
                if (v > bv) { bv = v; best = e; }
            }
            g_idx[tok] = best;
        }
        __syncthreads();
    }
}

// ---------------- count + scan + fill ----------------
__global__ void k_count() {
    int t = blockIdx.x * 256 + threadIdx.x;
    if (t < NTOK) atomicAdd(&g_counts[g_idx[t]], 1);
}
__global__ void k_scan() {
    int s = 0;
    for (int e = 0; e < NEXP; e++) { g_base[e] = s; s += g_counts[e]; }
    int nt = 0;
    for (int e = 0; e < NEXP; e++) {
        int c = g_counts[e];
        for (int r = 0; r < c; r += 128) {
            g_tile_e[nt] = e;
            g_tile_r[nt] = g_base[e] + r;
            g_tile_n[nt] = (c - r) < 128 ? (c - r) : 128;
            nt++;
        }
    }
    g_numtiles = nt;
}
__global__ void k_fill() {
    int t = blockIdx.x * 256 + threadIdx.x;
    if (t < NTOK) {
        int e = g_idx[t];
        int r = atomicAdd(&g_cursor[e], 1);
        g_perm[g_base[e] + r] = t;
    }
}

// ---------------- launch ----------------
extern "C" void kernel_launch(void* const* d_in, const int* in_sizes, int n_in,
                              void* d_out, int out_size) {
    const float* X  = (const float*)d_in[0];
    const float* w1 = (const float*)d_in[1];
    const float* b1 = (const float*)d_in[2];
    const float* w2 = (const float*)d_in[3];
    const float* b2 = (const float*)d_in[4];
    const float* eW = (const float*)d_in[5];
    const float* eb = (const float*)d_in[6];
    float* out = (float*)d_out;

    const int DSM = 2 * 2 * TILE_PB;  // 40960
    cudaFuncSetAttribute(k_gemm_mma<false>, cudaFuncAttributeMaxDynamicSharedMemorySize, DSM);
    cudaFuncSetAttribute(k_gemm_mma<true>,  cudaFuncAttributeMaxDynamicSharedMemorySize, DSM);

    k_init<<<1, 32>>>();
    k_convA<<<NTOK * HDIM / 1024, 256>>>(X);
    k_convW1<<<dim3(MDIM / 32, HDIM / 32, 1), dim3(32, 8)>>>(w1);
    k_convW2<<<dim3(HDIM / 32, HDIM / 32, NEXP), dim3(32, 8)>>>(eW);
    k_gemm_mma<false><<<dim3(NTOK / 128, MDIM / 128), 256, DSM>>>(b1, nullptr);
    k_scores<<<NTOK / 8, 256>>>(w2, b2);
    k_rescue<<<256, 256>>>(X, w1, b1, w2, b2);
    k_count<<<NTOK / 256, 256>>>();
    k_scan<<<1, 1>>>();
    k_fill<<<NTOK / 256, 256>>>();
    k_gemm_mma<true><<<dim3(MAX_TILES, HDIM / 128), 256, DSM>>>(eb, out);
}

// round 9
// speedup vs baseline: 1.5825x; 1.1058x over previous
#include <cuda_runtime.h>
#include <cuda_fp16.h>
#include <cstdint>

#define NTOK 16384
#define HDIM 1024
#define MDIM 512
#define NEXP 8
#define MAX_TILES 144
#define KC 64                 // K elements per chunk
#define NCK (HDIM / KC)       // 16 chunks
#define ROWB 144              // padded row bytes (64 fp16 = 128B + 16 pad)
#define TILEB (128 * ROWB)    // 18432
#define MAXFLAG 4096
#define GAP_THRESH 4e-3f

// ---------------- scratch ----------------
__device__ float  g_h[NTOK * MDIM];
__device__ __half g_X1[NTOK * HDIM];
__device__ __half g_W1a[MDIM * HDIM];
__device__ __half g_W2a[NEXP * HDIM * HDIM];
__device__ int g_idx[NTOK];
__device__ int g_counts[NEXP];
__device__ int g_base[NEXP];
__device__ int g_cursor[NEXP];
__device__ int g_perm[NTOK];
__device__ int g_tile_e[MAX_TILES];
__device__ int g_tile_r[MAX_TILES];
__device__ int g_tile_n[MAX_TILES];
__device__ int g_numtiles;
__device__ int g_flag[MAXFLAG];
__device__ int g_nflag;

// ---------------- helpers ----------------
__device__ __forceinline__ uint32_t smem_u32(const void* p) {
    uint32_t a;
    asm("{ .reg .u64 t; cvta.to.shared.u64 t, %1; cvt.u32.u64 %0, t; }" : "=r"(a) : "l"(p));
    return a;
}
__device__ __forceinline__ void cp16(uint32_t s, const void* g) {
    asm volatile("cp.async.cg.shared.global [%0], [%1], 16;" :: "r"(s), "l"(g));
}
#define CP_COMMIT() asm volatile("cp.async.commit_group;" ::: "memory")
#define CP_WAIT1()  asm volatile("cp.async.wait_group 1;" ::: "memory")
__device__ __forceinline__ void ldsm4(uint32_t r[4], uint32_t a) {
    asm volatile("ldmatrix.sync.aligned.m8n8.x4.shared.b16 {%0,%1,%2,%3}, [%4];"
                 : "=r"(r[0]), "=r"(r[1]), "=r"(r[2]), "=r"(r[3]) : "r"(a));
}
__device__ __forceinline__ void mma16816(float c[4], const uint32_t a[4], const uint32_t b[2]) {
    asm volatile(
        "mma.sync.aligned.m16n8k16.row.col.f32.f16.f16.f32 "
        "{%0,%1,%2,%3}, {%4,%5,%6,%7}, {%8,%9}, {%0,%1,%2,%3};"
        : "+f"(c[0]), "+f"(c[1]), "+f"(c[2]), "+f"(c[3])
        : "r"(a[0]), "r"(a[1]), "r"(a[2]), "r"(a[3]), "r"(b[0]), "r"(b[1]));
}

// ---------------- init ----------------
__global__ void k_init() {
    int t = threadIdx.x;
    if (t < NEXP) { g_counts[t] = 0; g_cursor[t] = 0; }
    if (t == 0) g_nflag = 0;
}

// ---------------- X -> fp16 ----------------
__global__ __launch_bounds__(256) void k_convA(const float* __restrict__ X) {
    int i = blockIdx.x * 256 + threadIdx.x;
    float4 v = ((const float4*)X)[i];
    __align__(8) __half a1[4];
    a1[0] = __float2half_rn(v.x); a1[1] = __float2half_rn(v.y);
    a1[2] = __float2half_rn(v.z); a1[3] = __float2half_rn(v.w);
    ((uint2*)g_X1)[i] = *(uint2*)a1;
}

// ---------------- w1 [K][N] -> [N][K] fp16 ----------------
__global__ void k_convW1(const float* __restrict__ src) {
    __shared__ float t[32][33];
    int n0 = blockIdx.x * 32, k0 = blockIdx.y * 32;
    int tx = threadIdx.x, ty = threadIdx.y;
#pragma unroll
    for (int j = 0; j < 4; j++)
        t[ty + 8 * j][tx] = src[(size_t)(k0 + ty + 8 * j) * MDIM + n0 + tx];
    __syncthreads();
#pragma unroll
    for (int j = 0; j < 4; j++) {
        int rr = ty + 8 * j;
        g_W1a[(size_t)(n0 + rr) * HDIM + k0 + tx] = __float2half_rn(t[tx][rr]);
    }
}

// ---------------- expert_W [E][K][N] -> [E][N][K] fp16 ----------------
__global__ void k_convW2(const float* __restrict__ src) {
    __shared__ float t[32][33];
    int e = blockIdx.z;
    const float* s = src + ((size_t)e << 20);
    __half* d1 = g_W2a + ((size_t)e << 20);
    int n0 = blockIdx.x * 32, k0 = blockIdx.y * 32;
    int tx = threadIdx.x, ty = threadIdx.y;
#pragma unroll
    for (int j = 0; j < 4; j++)
        t[ty + 8 * j][tx] = s[(size_t)(k0 + ty + 8 * j) * HDIM + n0 + tx];
    __syncthreads();
#pragma unroll
    for (int j = 0; j < 4; j++) {
        int rr = ty + 8 * j;
        d1[(size_t)(n0 + rr) * HDIM + k0 + tx] = __float2half_rn(t[tx][rr]);
    }
}

// ---------------- single-pass fp16 GEMM, K-chunk 64, 2-stage cp.async --------
template <bool GATHER>
__global__ __launch_bounds__(256, 2) void k_gemm_mma(const float* __restrict__ biasg,
                                                     float* __restrict__ outg) {
    constexpr int STAGE = 2 * TILEB;     // A + B
    __shared__ float sbias[128];
    __shared__ int tks[128];
    extern __shared__ char dsm[];
    const uint32_t sb = smem_u32(dsm);

    const int tid = threadIdx.x;
    const int wid = tid >> 5;
    const int lane = tid & 31;
    const int warp_m = wid >> 2;   // 0..1
    const int warp_n = wid & 3;    // 0..3

    int row0 = 0, nrows = 128, col0 = blockIdx.y * 128;
    const __half *A1, *B1;
    if (GATHER) {
        const int tile = blockIdx.x;
        if (tile >= g_numtiles) return;
        const int e = g_tile_e[tile];
        const int grs = g_tile_r[tile];
        nrows = g_tile_n[tile];
        if (tid < 128) {
            tks[tid] = g_perm[grs + (tid < nrows ? tid : 0)];
            sbias[tid] = biasg[(size_t)e * HDIM + col0 + tid];
        }
        A1 = g_X1;
        B1 = g_W2a + ((size_t)e << 20) + (size_t)col0 * HDIM;
    } else {
        row0 = blockIdx.x * 128;
        if (tid < 128) sbias[tid] = biasg[col0 + tid];
        A1 = g_X1;
        B1 = g_W1a + (size_t)col0 * HDIM;
    }
    __syncthreads();

    // cp.async mapping: 2048 chunks of 16B per stage, 8 per thread
    // cid: tile = cid>>10, row = (cid>>3)&127, seg = cid&7
    int c_tile[8], c_row[8], c_seg[8];
#pragma unroll
    for (int i = 0; i < 8; i++) {
        int cid = tid + i * 256;
        c_tile[i] = cid >> 10;
        c_row[i] = (cid >> 3) & 127;
        c_seg[i] = cid & 7;
    }

    auto issue = [&](int buf, int kbase) {
#pragma unroll
        for (int i = 0; i < 8; i++) {
            const int tile = c_tile[i], row = c_row[i], seg = c_seg[i];
            uint32_t sa = sb + buf * STAGE + tile * TILEB + row * ROWB + seg * 16;
            const __half* src;
            int grow;
            if (tile == 0) { src = A1; grow = GATHER ? tks[row] : row0 + row; }
            else           { src = B1; grow = row; }
            cp16(sa, src + (size_t)grow * HDIM + kbase + seg * 8);
        }
    };

    float acc[4][4][4];
#pragma unroll
    for (int mi = 0; mi < 4; mi++)
#pragma unroll
        for (int ni = 0; ni < 4; ni++)
#pragma unroll
            for (int k = 0; k < 4; k++) acc[mi][ni][k] = 0.0f;

    issue(0, 0);  CP_COMMIT();
    issue(1, KC); CP_COMMIT();

    const int lm = lane & 15, lh = lane >> 4;
    const uint32_t a_off = (uint32_t)((warp_m * 64 + lm) * ROWB + lh * 16);
    const uint32_t b_off = (uint32_t)((warp_n * 32 + lm) * ROWB + lh * 16);

    for (int c = 0; c < NCK; c++) {
        CP_WAIT1();
        __syncthreads();
        const int buf = c & 1;
        const uint32_t sA1 = sb + buf * STAGE;
        const uint32_t sB1 = sA1 + TILEB;

#pragma unroll
        for (int kh = 0; kh < 4; kh++) {
            uint32_t a1[4][4], b1f[4][2];
#pragma unroll
            for (int mi = 0; mi < 4; mi++)
                ldsm4(a1[mi], sA1 + a_off + mi * (16 * ROWB) + kh * 32);
#pragma unroll
            for (int nt = 0; nt < 2; nt++) {
                uint32_t r[4];
                ldsm4(r, sB1 + b_off + nt * (16 * ROWB) + kh * 32);
                b1f[nt * 2][0] = r[0]; b1f[nt * 2][1] = r[2];
                b1f[nt * 2 + 1][0] = r[1]; b1f[nt * 2 + 1][1] = r[3];
            }
#pragma unroll
            for (int mi = 0; mi < 4; mi++)
#pragma unroll
                for (int ni = 0; ni < 4; ni++)
                    mma16816(acc[mi][ni], a1[mi], b1f[ni]);
        }
        __syncthreads();
        if (c + 2 < NCK) issue(buf, (c + 2) * KC);
        CP_COMMIT();
    }

    // epilogue
    const int rbase = warp_m * 64 + (lane >> 2);
    const int cbase = warp_n * 32 + (lane & 3) * 2;
#pragma unroll
    for (int mi = 0; mi < 4; mi++) {
#pragma unroll
        for (int ni = 0; ni < 4; ni++) {
            const int r0 = rbase + mi * 16;
            const int cc = cbase + ni * 8;
            float v00 = acc[mi][ni][0] + sbias[cc];
            float v01 = acc[mi][ni][1] + sbias[cc + 1];
            float v10 = acc[mi][ni][2] + sbias[cc];
            float v11 = acc[mi][ni][3] + sbias[cc + 1];
            if (GATHER) {
                if (r0 < nrows) {
                    float* p = outg + (size_t)tks[r0] * HDIM + col0 + cc;
                    *(float2*)p = make_float2(v00, v01);
                }
                if (r0 + 8 < nrows) {
                    float* p = outg + (size_t)tks[r0 + 8] * HDIM + col0 + cc;
                    *(float2*)p = make_float2(v10, v11);
                }
            } else {
                float* p0 = g_h + (size_t)(row0 + r0) * MDIM + col0 + cc;
                float* p1 = g_h + (size_t)(row0 + r0 + 8) * MDIM + col0 + cc;
                *(float2*)p0 = make_float2(fmaxf(v00, 0.f), fmaxf(v01, 0.f));
                *(float2*)p1 = make_float2(fmaxf(v10, 0.f), fmaxf(v11, 0.f));
            }
        }
    }
}

// ---------------- scores + provisional argmax + counts + flagging ------------
__global__ __launch_bounds__(256) void k_scores(const float* __restrict__ w2,
                                                const float* __restrict__ b2) {
    __shared__ float sw2t[NEXP * MDIM];
    for (int i = threadIdx.x; i < MDIM * NEXP; i += 256) {
        int m = i / NEXP, e = i % NEXP;
        sw2t[e * MDIM + m] = w2[i];
    }
    __syncthreads();
    const int warp = threadIdx.x >> 5, lane = threadIdx.x & 31;
    const int t = blockIdx.x * 8 + warp;
    const float* hrow = g_h + (size_t)t * MDIM;
    float s[NEXP];
#pragma unroll
    for (int e = 0; e < NEXP; e++) s[e] = 0.0f;
    for (int m = lane; m < MDIM; m += 32) {
        float hv = hrow[m];
#pragma unroll
        for (int e = 0; e < NEXP; e++) s[e] = fmaf(hv, sw2t[e * MDIM + m], s[e]);
    }
#pragma unroll
    for (int e = 0; e < NEXP; e++)
#pragma unroll
        for (int off = 16; off; off >>= 1) s[e] += __shfl_xor_sync(0xffffffffu, s[e], off);
    if (lane == 0) {
        int best = 0;
        float bv = s[0] + b2[0], second = -1e30f;
#pragma unroll
        for (int e = 1; e < NEXP; e++) {
            float v = s[e] + b2[e];
            if (v > bv) { second = bv; bv = v; best = e; }
            else if (v > second) second = v;
        }
        g_idx[t] = best;
        atomicAdd(&g_counts[best], 1);
        if (bv - second < GAP_THRESH) {
            int slot = atomicAdd(&g_nflag, 1);
            if (slot < MAXFLAG) g_flag[slot] = t;
        }
    }
}

// ---------------- exact fp32 rescue (one block per flagged token, ILP4) ------
__global__ __launch_bounds__(256) void k_rescue(const float* __restrict__ X,
                                                const float* __restrict__ w1,
                                                const float* __restrict__ b1,
                                                const float* __restrict__ w2,
                                                const float* __restrict__ b2) {
    __shared__ float sx[HDIM];
    __shared__ float ssc[NEXP];
    const int tid = threadIdx.x;
    int n = g_nflag;
    if (n > MAXFLAG) n = MAXFLAG;
    for (int i = blockIdx.x; i < n; i += gridDim.x) {
        const int tok = g_flag[i];
        for (int k = tid; k < HDIM; k += 256) sx[k] = X[(size_t)tok * HDIM + k];
        if (tid < NEXP) ssc[tid] = 0.0f;
        __syncthreads();
        float sc[NEXP];
#pragma unroll
        for (int e = 0; e < NEXP; e++) sc[e] = 0.0f;
#pragma unroll
        for (int half = 0; half < 2; half++) {
            const int nc = tid + half * 256;
            float a0 = 0.f, a1 = 0.f, a2 = 0.f, a3 = 0.f;
#pragma unroll 4
            for (int k = 0; k < HDIM; k += 4) {
                a0 = fmaf(sx[k + 0], __ldg(&w1[(size_t)(k + 0) * MDIM + nc]), a0);
                a1 = fmaf(sx[k + 1], __ldg(&w1[(size_t)(k + 1) * MDIM + nc]), a1);
                a2 = fmaf(sx[k + 2], __ldg(&w1[(size_t)(k + 2) * MDIM + nc]), a2);
                a3 = fmaf(sx[k + 3], __ldg(&w1[(size_t)(k + 3) * MDIM + nc]), a3);
            }
            float a = fmaxf((a0 + a1) + (a2 + a3) + b1[nc], 0.0f);
#pragma unroll
            for (int e = 0; e < NEXP; e++) sc[e] = fmaf(a, w2[nc * NEXP + e], sc[e]);
        }
#pragma unroll
        for (int e = 0; e < NEXP; e++) {
#pragma unroll
            for (int off = 16; off; off >>= 1) sc[e] += __shfl_xor_sync(0xffffffffu, sc[e], off);
            if ((tid & 31) == 0) atomicAdd(&ssc[e], sc[e]);
        }
        __syncthreads();
        if (tid == 0) {
            int best = 0;
            float bv = ssc[0] + b2[0];
#pragma unroll
            for (int e = 1; e < NEXP; e++) {
                float v = ssc[e] + b2[e];
                if (v > bv) { bv = v; best = e; }
            }
            int old = g_idx[tok];
            if (best != old) {
                g_idx[tok] = best;
                atomicSub(&g_counts[old], 1);
                atomicAdd(&g_counts[best], 1);
            }
        }
        __syncthreads();
    }
}

// ---------------- scan + fill ----------------
__global__ void k_scan() {
    int s = 0;
    for (int e = 0; e < NEXP; e++) { g_base[e] = s; s += g_counts[e]; }
    int nt = 0;
    for (int e = 0; e < NEXP; e++) {
        int c = g_counts[e];
        for (int r = 0; r < c; r += 128) {
            g_tile_e[nt] = e;
            g_tile_r[nt] = g_base[e] + r;
            g_tile_n[nt] = (c - r) < 128 ? (c - r) : 128;
            nt++;
        }
    }
    g_numtiles = nt;
}
__global__ void k_fill() {
    int t = blockIdx.x * 256 + threadIdx.x;
    if (t < NTOK) {
        int e = g_idx[t];
        int r = atomicAdd(&g_cursor[e], 1);
        g_perm[g_base[e] + r] = t;
    }
}

// ---------------- launch ----------------
extern "C" void kernel_launch(void* const* d_in, const int* in_sizes, int n_in,
                              void* d_out, int out_size) {
    const float* X  = (const float*)d_in[0];
    const float* w1 = (const float*)d_in[1];
    const float* b1 = (const float*)d_in[2];
    const float* w2 = (const float*)d_in[3];
    const float* b2 = (const float*)d_in[4];
    const float* eW = (const float*)d_in[5];
    const float* eb = (const float*)d_in[6];
    float* out = (float*)d_out;

    const int DSM = 2 * 2 * TILEB;  // 73728
    cudaFuncSetAttribute(k_gemm_mma<false>, cudaFuncAttributeMaxDynamicSharedMemorySize, DSM);
    cudaFuncSetAttribute(k_gemm_mma<true>,  cudaFuncAttributeMaxDynamicSharedMemorySize, DSM);

    k_init<<<1, 32>>>();
    k_convA<<<NTOK * HDIM / 1024, 256>>>(X);
    k_convW1<<<dim3(MDIM / 32, HDIM / 32, 1), dim3(32, 8)>>>(w1);
    k_convW2<<<dim3(HDIM / 32, HDIM / 32, NEXP), dim3(32, 8)>>>(eW);
    k_gemm_mma<false><<<dim3(NTOK / 128, MDIM / 128), 256, DSM>>>(b1, nullptr);
    k_scores<<<NTOK / 8, 256>>>(w2, b2);
    k_rescue<<<256, 256>>>(X, w1, b1, w2, b2);
    k_scan<<<1, 1>>>();
    k_fill<<<NTOK / 256, 256>>>();
    k_gemm_mma<true><<<dim3(MAX_TILES, HDIM / 128), 256, DSM>>>(eb, out);
}